// round 11
// baseline (speedup 1.0000x reference)
#include <cuda_runtime.h>
#include <cuda_bf16.h>

// Problem constants (fixed shapes for GAT_68762426409265)
#define NN  100000          // nodes
#define FIN 256             // input features
#define HID 64              // hidden
#define NC  40              // classes
#define EE  1600000         // edges (without self loops)
#define ET  (EE + NN)       // edges + self loops

// ---------------- device scratch (static, no allocation) ----------------
__device__ float g_h1[(size_t)NN * HID];     // layer1 projection
__device__ float g_out1[(size_t)NN * HID];   // layer1 aggregated (relu'd)
__device__ float g_h2[(size_t)NN * NC];      // layer2 projection
__device__ float g_s1[NN];
__device__ float g_d1[NN];
__device__ float g_s2[NN];
__device__ float g_d2[NN];
__device__ int   g_cnt[NN];
__device__ int   g_scan[NN];
__device__ int   g_rowptr[NN + 1];
__device__ int   g_cursor[NN];
__device__ int   g_bsum[128];
__device__ int2  g_edge[ET];                 // packed {src, ew-bits}

// ---------------- small asm helpers ----------------
__device__ __forceinline__ unsigned f2tf(float x) {
    unsigned r; asm("cvt.rna.tf32.f32 %0, %1;" : "=r"(r) : "f"(x)); return r;
}
__device__ __forceinline__ void mma_tf32(float* c, const unsigned* a, const unsigned* b) {
    asm volatile("mma.sync.aligned.m16n8k8.row.col.f32.tf32.tf32.f32 "
                 "{%0,%1,%2,%3}, {%4,%5,%6,%7}, {%8,%9}, {%0,%1,%2,%3};"
                 : "+f"(c[0]), "+f"(c[1]), "+f"(c[2]), "+f"(c[3])
                 : "r"(a[0]), "r"(a[1]), "r"(a[2]), "r"(a[3]),
                   "r"(b[0]), "r"(b[1]));
}
__device__ __forceinline__ unsigned long long pk2(float x, float y) {
    unsigned long long r;
    asm("mov.b64 %0, {%1,%2};" : "=l"(r) : "f"(x), "f"(y));
    return r;
}
__device__ __forceinline__ float2 upk2(unsigned long long v) {
    float x, y;
    asm("mov.b64 {%0,%1}, %2;" : "=f"(x), "=f"(y) : "l"(v));
    return make_float2(x, y);
}
__device__ __forceinline__ unsigned long long ffma2(unsigned long long a,
                                                    unsigned long long b,
                                                    unsigned long long c) {
    unsigned long long d;
    asm("fma.rn.f32x2 %0, %1, %2, %3;" : "=l"(d) : "l"(a), "l"(b), "l"(c));
    return d;
}

// ---------------- CSR build ----------------
__global__ void zero_cnt_kernel() {
    int i = blockIdx.x * blockDim.x + threadIdx.x;
    if (i < NN) g_cnt[i] = 0;
}

__global__ void hist_kernel(const int* __restrict__ dst) {
    int e = blockIdx.x * blockDim.x + threadIdx.x;
    if (e >= ET) return;
    int d = (e < EE) ? dst[e] : (e - EE);
    atomicAdd(&g_cnt[d], 1);
}

__global__ void scan1_kernel() {
    __shared__ int tmp[1024];
    int t = threadIdx.x;
    int i = blockIdx.x * 1024 + t;
    tmp[t] = (i < NN) ? g_cnt[i] : 0;
    __syncthreads();
    #pragma unroll
    for (int off = 1; off < 1024; off <<= 1) {
        int x = 0;
        if (t >= off) x = tmp[t - off];
        __syncthreads();
        tmp[t] += x;
        __syncthreads();
    }
    if (i < NN) g_scan[i] = tmp[t];
    if (t == 1023) g_bsum[blockIdx.x] = tmp[1023];
}

// Fused scan2 + scan3 + cursor
__global__ void scan23_kernel(int nb) {
    __shared__ int bs[128];
    int t = threadIdx.x;
    if (t < 128) bs[t] = (t < nb) ? g_bsum[t] : 0;
    __syncthreads();
    #pragma unroll
    for (int off = 1; off < 128; off <<= 1) {
        int x = 0;
        if (t < 128 && t >= off) x = bs[t - off];
        __syncthreads();
        if (t < 128) bs[t] += x;
        __syncthreads();
    }
    int i = blockIdx.x * 1024 + t;
    if (i < NN) {
        int blk  = i >> 10;
        int boff = blk ? bs[blk - 1] : 0;
        int inc  = g_scan[i] + boff;
        g_rowptr[i + 1] = inc;
        g_cursor[i]     = inc - g_cnt[i];
        if (i == 0) g_rowptr[0] = 0;
    }
}

__global__ void fill_kernel(const int* __restrict__ src, const int* __restrict__ dst,
                            const float* __restrict__ ew) {
    int e = blockIdx.x * blockDim.x + threadIdx.x;
    if (e >= ET) return;
    int s, d;
    float w;
    if (e < EE) { s = src[e]; d = dst[e]; w = ew[e]; }
    else        { s = d = e - EE; w = 1.0f; }
    int pos = atomicAdd(&g_cursor[d], 1);
    g_edge[pos] = make_int2(s, __float_as_int(w));   // single 8B scattered store
}

// ---------------- GEMM1: h1 = x @ W1, [NN,256]@[256,64], 3xTF32 -------------------
// BM=128, BK=16, BN=64. 8 warps: wm 0..3 (32 rows), wn 0..1 (32 cols).
// TF32 hi/lo conversion done ONCE per element at tile-store time; mainloop is pure
// LDS+MMA. Pipelining via register staging: next raw tile LDG'd while MMA runs.
// Fused epilogue: s1 = h1 . a1s, d1 = h1 . a1d.
__global__ __launch_bounds__(256) void gemm1_tc(const float* __restrict__ X,
                                                const float* __restrict__ W,
                                                const float* __restrict__ A1S,
                                                const float* __restrict__ A1D) {
    __shared__ unsigned Ah[128][20];   // pad 20: conflict-free frag loads
    __shared__ unsigned Al[128][20];
    __shared__ unsigned Bh[16][72];    // pad 72
    __shared__ unsigned Bl[16][72];
    __shared__ float    s_sm[2][128];
    __shared__ float    d_sm[2][128];

    const int t    = threadIdx.x;
    const int lane = t & 31;
    const int w    = t >> 5;
    const int wm   = w >> 1;
    const int wn   = w & 1;
    const int m0   = blockIdx.x * 128;

    // per-thread load coordinates
    const int ar0 = t >> 2,          ac0 = (t & 3) << 2;          // A chunk 0
    const int ar1 = (t + 256) >> 2,  ac1 = ((t + 256) & 3) << 2;  // A chunk 1
    const int br  = t >> 4,          bc  = (t & 15) << 2;         // B chunk
    const int gr0 = m0 + ar0, gr1 = m0 + ar1;
    const bool ok0 = gr0 < NN, ok1 = gr1 < NN;
    const float* pA0 = X + (size_t)(ok0 ? gr0 : 0) * FIN + ac0;
    const float* pA1 = X + (size_t)(ok1 ? gr1 : 0) * FIN + ac1;
    const float* pB  = W + (size_t)br * HID + bc;

    float4 sa0, sa1, sb;   // register staging for the next tile

    auto load_raw = [&](int kc) {
        sa0 = ok0 ? *(const float4*)(pA0 + kc) : make_float4(0.f, 0.f, 0.f, 0.f);
        sa1 = ok1 ? *(const float4*)(pA1 + kc) : make_float4(0.f, 0.f, 0.f, 0.f);
        sb  = *(const float4*)(pB + (size_t)kc * HID);
    };
    auto store_conv = [&]() {
        unsigned h;
        h = f2tf(sa0.x); Ah[ar0][ac0 + 0] = h; Al[ar0][ac0 + 0] = f2tf(sa0.x - __uint_as_float(h));
        h = f2tf(sa0.y); Ah[ar0][ac0 + 1] = h; Al[ar0][ac0 + 1] = f2tf(sa0.y - __uint_as_float(h));
        h = f2tf(sa0.z); Ah[ar0][ac0 + 2] = h; Al[ar0][ac0 + 2] = f2tf(sa0.z - __uint_as_float(h));
        h = f2tf(sa0.w); Ah[ar0][ac0 + 3] = h; Al[ar0][ac0 + 3] = f2tf(sa0.w - __uint_as_float(h));
        h = f2tf(sa1.x); Ah[ar1][ac1 + 0] = h; Al[ar1][ac1 + 0] = f2tf(sa1.x - __uint_as_float(h));
        h = f2tf(sa1.y); Ah[ar1][ac1 + 1] = h; Al[ar1][ac1 + 1] = f2tf(sa1.y - __uint_as_float(h));
        h = f2tf(sa1.z); Ah[ar1][ac1 + 2] = h; Al[ar1][ac1 + 2] = f2tf(sa1.z - __uint_as_float(h));
        h = f2tf(sa1.w); Ah[ar1][ac1 + 3] = h; Al[ar1][ac1 + 3] = f2tf(sa1.w - __uint_as_float(h));
        h = f2tf(sb.x);  Bh[br][bc + 0]  = h; Bl[br][bc + 0]  = f2tf(sb.x - __uint_as_float(h));
        h = f2tf(sb.y);  Bh[br][bc + 1]  = h; Bl[br][bc + 1]  = f2tf(sb.y - __uint_as_float(h));
        h = f2tf(sb.z);  Bh[br][bc + 2]  = h; Bl[br][bc + 2]  = f2tf(sb.z - __uint_as_float(h));
        h = f2tf(sb.w);  Bh[br][bc + 3]  = h; Bl[br][bc + 3]  = f2tf(sb.w - __uint_as_float(h));
    };

    float acc[2][4][4];
    #pragma unroll
    for (int i = 0; i < 2; i++)
        #pragma unroll
        for (int j = 0; j < 4; j++)
            #pragma unroll
            for (int k = 0; k < 4; k++) acc[i][j][k] = 0.0f;

    load_raw(0);

    for (int tile = 0; tile < 16; tile++) {
        store_conv();
        __syncthreads();
        if (tile < 15) load_raw((tile + 1) * 16);   // LDG in flight during MMA below

        #pragma unroll
        for (int ks = 0; ks < 2; ks++) {
            unsigned bh[4][2], bl[4][2];
            #pragma unroll
            for (int nt = 0; nt < 4; nt++) {
                int n = wn * 32 + nt * 8 + (lane >> 2);
                int k = ks * 8 + (lane & 3);
                bh[nt][0] = Bh[k][n];     bh[nt][1] = Bh[k + 4][n];
                bl[nt][0] = Bl[k][n];     bl[nt][1] = Bl[k + 4][n];
            }
            #pragma unroll
            for (int mt = 0; mt < 2; mt++) {
                int r = wm * 32 + mt * 16 + (lane >> 2);
                int c = ks * 8 + (lane & 3);
                unsigned ah[4] = { Ah[r][c], Ah[r + 8][c], Ah[r][c + 4], Ah[r + 8][c + 4] };
                unsigned al[4] = { Al[r][c], Al[r + 8][c], Al[r][c + 4], Al[r + 8][c + 4] };
                #pragma unroll
                for (int nt = 0; nt < 4; nt++) {
                    mma_tf32(acc[mt][nt], ah, bh[nt]);
                    mma_tf32(acc[mt][nt], ah, bl[nt]);
                    mma_tf32(acc[mt][nt], al, bh[nt]);
                }
            }
        }
        __syncthreads();
    }

    // epilogue: store h1 + fused s/d dot products
    float a_s[8], a_d[8];
    #pragma unroll
    for (int nt = 0; nt < 4; nt++) {
        int c0 = wn * 32 + nt * 8 + (lane & 3) * 2;
        a_s[nt * 2]     = A1S[c0];
        a_s[nt * 2 + 1] = A1S[c0 + 1];
        a_d[nt * 2]     = A1D[c0];
        a_d[nt * 2 + 1] = A1D[c0 + 1];
    }

    #pragma unroll
    for (int mt = 0; mt < 2; mt++) {
        int r0 = m0 + wm * 32 + mt * 16 + (lane >> 2);
        float sp0 = 0.f, dp0 = 0.f, sp1 = 0.f, dp1 = 0.f;
        #pragma unroll
        for (int nt = 0; nt < 4; nt++) {
            int c0 = wn * 32 + nt * 8 + (lane & 3) * 2;
            if (r0 < NN)
                *(float2*)(g_h1 + (size_t)r0 * HID + c0) =
                    make_float2(acc[mt][nt][0], acc[mt][nt][1]);
            if (r0 + 8 < NN)
                *(float2*)(g_h1 + (size_t)(r0 + 8) * HID + c0) =
                    make_float2(acc[mt][nt][2], acc[mt][nt][3]);
            sp0 = fmaf(acc[mt][nt][0], a_s[nt * 2],     sp0);
            sp0 = fmaf(acc[mt][nt][1], a_s[nt * 2 + 1], sp0);
            sp1 = fmaf(acc[mt][nt][2], a_s[nt * 2],     sp1);
            sp1 = fmaf(acc[mt][nt][3], a_s[nt * 2 + 1], sp1);
            dp0 = fmaf(acc[mt][nt][0], a_d[nt * 2],     dp0);
            dp0 = fmaf(acc[mt][nt][1], a_d[nt * 2 + 1], dp0);
            dp1 = fmaf(acc[mt][nt][2], a_d[nt * 2],     dp1);
            dp1 = fmaf(acc[mt][nt][3], a_d[nt * 2 + 1], dp1);
        }
        #pragma unroll
        for (int off = 1; off < 4; off <<= 1) {
            sp0 += __shfl_xor_sync(0xffffffffu, sp0, off);
            sp1 += __shfl_xor_sync(0xffffffffu, sp1, off);
            dp0 += __shfl_xor_sync(0xffffffffu, dp0, off);
            dp1 += __shfl_xor_sync(0xffffffffu, dp1, off);
        }
        if ((lane & 3) == 0) {
            int lr = wm * 32 + mt * 16 + (lane >> 2);
            s_sm[wn][lr]     = sp0;
            s_sm[wn][lr + 8] = sp1;
            d_sm[wn][lr]     = dp0;
            d_sm[wn][lr + 8] = dp1;
        }
    }
    __syncthreads();
    if (t < 128) {
        int gr = m0 + t;
        if (gr < NN) {
            g_s1[gr] = s_sm[0][t] + s_sm[1][t];
            g_d1[gr] = d_sm[0][t] + d_sm[1][t];
        }
    }
}

// ---------------- GEMM2: h2 = out1 @ W2 (out1 already relu'd), fused s2/d2 ----------
__global__ __launch_bounds__(320) void gemm2_kernel(const float* __restrict__ W2,
                                                    const float* __restrict__ A2S,
                                                    const float* __restrict__ A2D) {
    __shared__ float hs[64][65];
    __shared__ unsigned long long ws2[64][20];
    __shared__ float s_sm2[10][64];
    __shared__ float d_sm2[10][64];
    const int t  = threadIdx.x;              // 320 threads
    const int tx = t % 10;
    const int ty = t / 10;
    const int m0 = blockIdx.x * 64;

    for (int idx = t; idx < 64 * 64; idx += 320) {
        int r = idx >> 6, c = idx & 63;
        int gr = m0 + r;
        hs[r][c] = (gr < NN) ? g_out1[(size_t)gr * HID + c] : 0.0f;
    }
    for (int idx = t; idx < 64 * 20; idx += 320) {
        int r = idx / 20, j = idx % 20;
        float2 v = *(const float2*)(W2 + (size_t)r * NC + j * 2);
        ws2[r][j] = pk2(v.x, v.y);
    }
    __syncthreads();

    if (ty < 32) {
        unsigned long long acc[2][2] = {{0ull, 0ull}, {0ull, 0ull}};
        #pragma unroll
        for (int k = 0; k < 64; k++) {
            unsigned long long b0 = ws2[k][tx * 2];
            unsigned long long b1 = ws2[k][tx * 2 + 1];
            #pragma unroll
            for (int i = 0; i < 2; i++) {
                float a = hs[ty * 2 + i][k];
                unsigned long long aa = pk2(a, a);
                acc[i][0] = ffma2(aa, b0, acc[i][0]);
                acc[i][1] = ffma2(aa, b1, acc[i][1]);
            }
        }
        float as0 = A2S[tx * 4], as1 = A2S[tx * 4 + 1], as2 = A2S[tx * 4 + 2], as3 = A2S[tx * 4 + 3];
        float ad0 = A2D[tx * 4], ad1 = A2D[tx * 4 + 1], ad2 = A2D[tx * 4 + 2], ad3 = A2D[tx * 4 + 3];
        #pragma unroll
        for (int i = 0; i < 2; i++) {
            int row = m0 + ty * 2 + i;
            float2 lo = upk2(acc[i][0]);
            float2 hi = upk2(acc[i][1]);
            if (row < NN) {
                float4 v = make_float4(lo.x, lo.y, hi.x, hi.y);
                *(float4*)(g_h2 + (size_t)row * NC + tx * 4) = v;
            }
            s_sm2[tx][ty * 2 + i] = lo.x * as0 + lo.y * as1 + hi.x * as2 + hi.y * as3;
            d_sm2[tx][ty * 2 + i] = lo.x * ad0 + lo.y * ad1 + hi.x * ad2 + hi.y * ad3;
        }
    }
    __syncthreads();
    if (t < 64) {
        int gr = m0 + t;
        if (gr < NN) {
            float ss = 0.f, dd = 0.f;
            #pragma unroll
            for (int j = 0; j < 10; j++) { ss += s_sm2[j][t]; dd += d_sm2[j][t]; }
            g_s2[gr] = ss;
            g_d2[gr] = dd;
        }
    }
}

// ---------------- aggregation: warp per dst node, fused pass, MLP=4 ----------------
// Packed int2 edge list: one 8B load per edge. Inactive lanes carry (w=0, src=0) so
// the x4-unrolled broadcast loop needs no guards.
template <int D, bool RELU>
__global__ __launch_bounds__(256) void agg_kernel(const float* __restrict__ H,
                                                  const float* __restrict__ S,
                                                  const float* __restrict__ DA,
                                                  float* __restrict__ OUT) {
    int v    = (blockIdx.x * blockDim.x + threadIdx.x) >> 5;
    int lane = threadIdx.x & 31;
    if (v >= NN) return;
    int p0 = g_rowptr[v], p1 = g_rowptr[v + 1];
    float dv = DA[v];

    int col = lane * 2;
    if (col > D - 2) col = D - 2;   // clamp (D=40: lanes 20..31 duplicate, don't store)

    float2 acc = make_float2(0.0f, 0.0f);
    float denom = 0.0f;

    for (int base = p0; base < p1; base += 32) {
        int p = base + lane;
        float wl = 0.0f;
        int   svl = 0;
        if (p < p1) {
            int2 e = g_edge[p];
            svl = e.x;
            float sc = S[svl] + dv;
            sc = sc > 0.0f ? sc : 0.2f * sc;
            float el = __expf(sc);
            denom += el;                               // denominator: exp only (no ew)
            wl = el * __int_as_float(e.y);             // numerator weight: exp * ew
        }
        int nj  = p1 - base; if (nj > 32) nj = 32;
        int njp = (nj + 3) & ~3;             // pad: extra lanes have w=0, src=0
        for (int j = 0; j < njp; j += 4) {
            float w0 = __shfl_sync(0xffffffffu, wl, j);
            float w1 = __shfl_sync(0xffffffffu, wl, j + 1);
            float w2 = __shfl_sync(0xffffffffu, wl, j + 2);
            float w3 = __shfl_sync(0xffffffffu, wl, j + 3);
            int   s0 = __shfl_sync(0xffffffffu, svl, j);
            int   s1 = __shfl_sync(0xffffffffu, svl, j + 1);
            int   s2 = __shfl_sync(0xffffffffu, svl, j + 2);
            int   s3 = __shfl_sync(0xffffffffu, svl, j + 3);
            float2 h0 = *(const float2*)(H + (size_t)s0 * D + col);
            float2 h1 = *(const float2*)(H + (size_t)s1 * D + col);
            float2 h2 = *(const float2*)(H + (size_t)s2 * D + col);
            float2 h3 = *(const float2*)(H + (size_t)s3 * D + col);
            acc.x = fmaf(w0, h0.x, acc.x);  acc.y = fmaf(w0, h0.y, acc.y);
            acc.x = fmaf(w1, h1.x, acc.x);  acc.y = fmaf(w1, h1.y, acc.y);
            acc.x = fmaf(w2, h2.x, acc.x);  acc.y = fmaf(w2, h2.y, acc.y);
            acc.x = fmaf(w3, h3.x, acc.x);  acc.y = fmaf(w3, h3.y, acc.y);
        }
    }
    #pragma unroll
    for (int off = 16; off; off >>= 1)
        denom += __shfl_xor_sync(0xffffffffu, denom, off);
    float inv = 1.0f / denom;   // >0 guaranteed: every node has a self loop

    if (lane * 2 < D) {
        float ox = acc.x * inv, oy = acc.y * inv;
        if (RELU) { ox = ox > 0.f ? ox : 0.f; oy = oy > 0.f ? oy : 0.f; }
        *(float2*)(OUT + (size_t)v * D + col) = make_float2(ox, oy);
    }
}

// ---------------- launch ----------------
extern "C" void kernel_launch(void* const* d_in, const int* in_sizes, int n_in,
                              void* d_out, int out_size) {
    const float* x   = (const float*)d_in[0];
    const int*   ei  = (const int*)  d_in[1];
    const float* ew  = (const float*)d_in[2];
    const float* W1  = (const float*)d_in[3];
    const float* a1s = (const float*)d_in[4];
    const float* a1d = (const float*)d_in[5];
    const float* W2  = (const float*)d_in[6];
    const float* a2s = (const float*)d_in[7];
    const float* a2d = (const float*)d_in[8];
    float* out = (float*)d_out;

    const int* srcA = ei;
    const int* dstA = ei + EE;

    float *ph1, *pout1, *ph2, *ps1, *pd1, *ps2, *pd2;
    cudaGetSymbolAddress((void**)&ph1,   g_h1);
    cudaGetSymbolAddress((void**)&pout1, g_out1);
    cudaGetSymbolAddress((void**)&ph2,   g_h2);
    cudaGetSymbolAddress((void**)&ps1,   g_s1);
    cudaGetSymbolAddress((void**)&pd1,   g_d1);
    cudaGetSymbolAddress((void**)&ps2,   g_s2);
    cudaGetSymbolAddress((void**)&pd2,   g_d2);

    // Capture-safe side stream + fork/join events
    static cudaStream_t s2 = nullptr;
    static cudaEvent_t  evF = nullptr, evJ = nullptr;
    if (!s2) {
        cudaStreamCreateWithFlags(&s2, cudaStreamNonBlocking);
        cudaEventCreateWithFlags(&evF, cudaEventDisableTiming);
        cudaEventCreateWithFlags(&evJ, cudaEventDisableTiming);
    }

    const int TPB = 256;
    const int nb  = (NN + 1023) / 1024;

    // Fork: CSR build on side stream, gemm1 on main stream (issue #4 for ncu capture)
    cudaEventRecord(evF, 0);
    cudaStreamWaitEvent(s2, evF, 0);
    zero_cnt_kernel<<<(NN + TPB - 1) / TPB, TPB, 0, s2>>>();
    hist_kernel<<<(ET + TPB - 1) / TPB, TPB, 0, s2>>>(dstA);
    scan1_kernel<<<nb, 1024, 0, s2>>>();
    gemm1_tc<<<(NN + 127) / 128, 256>>>(x, W1, a1s, a1d);       // main stream, issue #4
    scan23_kernel<<<nb, 1024, 0, s2>>>(nb);
    fill_kernel<<<(ET + TPB - 1) / TPB, TPB, 0, s2>>>(srcA, dstA, ew);
    cudaEventRecord(evJ, s2);

    // Join, then the serial tail
    cudaStreamWaitEvent(0, evJ, 0);
    agg_kernel<HID, true><<<(NN * 32 + TPB - 1) / TPB, TPB>>>(ph1, ps1, pd1, pout1);
    gemm2_kernel<<<(NN + 63) / 64, 320>>>(W2, a2s, a2d);
    agg_kernel<NC, false><<<(NN * 32 + TPB - 1) / TPB, TPB>>>(ph2, ps2, pd2, out);
}

// round 12
// speedup vs baseline: 1.1240x; 1.1240x over previous
#include <cuda_runtime.h>
#include <cuda_bf16.h>

// Problem constants (fixed shapes for GAT_68762426409265)
#define NN  100000          // nodes
#define FIN 256             // input features
#define HID 64              // hidden
#define NC  40              // classes
#define EE  1600000         // edges (without self loops)
#define ET  (EE + NN)       // edges + self loops

// ---------------- device scratch (static, no allocation) ----------------
__device__ float    g_h1[(size_t)NN * HID];     // layer1 projection
__device__ float    g_out1[(size_t)NN * HID];   // layer1 aggregated (relu'd)
__device__ float    g_h2[(size_t)NN * NC];      // layer2 projection
__device__ float    g_s1[NN];
__device__ float    g_d1[NN];
__device__ float    g_s2[NN];
__device__ float    g_d2[NN];
__device__ int      g_cnt[NN];
__device__ int      g_scan[NN];
__device__ int      g_rowptr[NN + 1];
__device__ int      g_cursor[NN];
__device__ int      g_bsum[128];
__device__ int2     g_edge[ET];                 // packed {src, ew-bits}
__device__ unsigned g_W1hl[FIN * 128];          // W1 pre-split: row k = [64 hi | 64 lo]

// ---------------- small asm helpers ----------------
__device__ __forceinline__ unsigned f2tf(float x) {
    unsigned r; asm("cvt.rna.tf32.f32 %0, %1;" : "=r"(r) : "f"(x)); return r;
}
__device__ __forceinline__ void mma_tf32(float* c, const unsigned* a, const unsigned* b) {
    asm volatile("mma.sync.aligned.m16n8k8.row.col.f32.tf32.tf32.f32 "
                 "{%0,%1,%2,%3}, {%4,%5,%6,%7}, {%8,%9}, {%0,%1,%2,%3};"
                 : "+f"(c[0]), "+f"(c[1]), "+f"(c[2]), "+f"(c[3])
                 : "r"(a[0]), "r"(a[1]), "r"(a[2]), "r"(a[3]),
                   "r"(b[0]), "r"(b[1]));
}
__device__ __forceinline__ unsigned long long pk2(float x, float y) {
    unsigned long long r;
    asm("mov.b64 %0, {%1,%2};" : "=l"(r) : "f"(x), "f"(y));
    return r;
}
__device__ __forceinline__ float2 upk2(unsigned long long v) {
    float x, y;
    asm("mov.b64 {%0,%1}, %2;" : "=f"(x), "=f"(y) : "l"(v));
    return make_float2(x, y);
}
__device__ __forceinline__ unsigned long long ffma2(unsigned long long a,
                                                    unsigned long long b,
                                                    unsigned long long c) {
    unsigned long long d;
    asm("fma.rn.f32x2 %0, %1, %2, %3;" : "=l"(d) : "l"(a), "l"(b), "l"(c));
    return d;
}
__device__ __forceinline__ void cpa16(void* dst_smem, const void* src, bool pred) {
    unsigned d = (unsigned)__cvta_generic_to_shared(dst_smem);
    int sz = pred ? 16 : 0;   // src-size 0 => zero-fill
    asm volatile("cp.async.cg.shared.global [%0], [%1], 16, %2;\n"
                 :: "r"(d), "l"(src), "r"(sz));
}
__device__ __forceinline__ void cpa_commit() {
    asm volatile("cp.async.commit_group;\n" ::: "memory");
}
template <int N>
__device__ __forceinline__ void cpa_wait() {
    asm volatile("cp.async.wait_group %0;\n" :: "n"(N) : "memory");
}

// ---------------- CSR build ----------------
__global__ void zero_cnt_kernel() {
    int i = blockIdx.x * blockDim.x + threadIdx.x;
    if (i < NN) g_cnt[i] = 0;
}

__global__ void hist_kernel(const int* __restrict__ dst) {
    int e = blockIdx.x * blockDim.x + threadIdx.x;
    if (e >= ET) return;
    int d = (e < EE) ? dst[e] : (e - EE);
    atomicAdd(&g_cnt[d], 1);
}

__global__ void scan1_kernel() {
    __shared__ int tmp[1024];
    int t = threadIdx.x;
    int i = blockIdx.x * 1024 + t;
    tmp[t] = (i < NN) ? g_cnt[i] : 0;
    __syncthreads();
    #pragma unroll
    for (int off = 1; off < 1024; off <<= 1) {
        int x = 0;
        if (t >= off) x = tmp[t - off];
        __syncthreads();
        tmp[t] += x;
        __syncthreads();
    }
    if (i < NN) g_scan[i] = tmp[t];
    if (t == 1023) g_bsum[blockIdx.x] = tmp[1023];
}

// Fused scan2 + scan3 + cursor
__global__ void scan23_kernel(int nb) {
    __shared__ int bs[128];
    int t = threadIdx.x;
    if (t < 128) bs[t] = (t < nb) ? g_bsum[t] : 0;
    __syncthreads();
    #pragma unroll
    for (int off = 1; off < 128; off <<= 1) {
        int x = 0;
        if (t < 128 && t >= off) x = bs[t - off];
        __syncthreads();
        if (t < 128) bs[t] += x;
        __syncthreads();
    }
    int i = blockIdx.x * 1024 + t;
    if (i < NN) {
        int blk  = i >> 10;
        int boff = blk ? bs[blk - 1] : 0;
        int inc  = g_scan[i] + boff;
        g_rowptr[i + 1] = inc;
        g_cursor[i]     = inc - g_cnt[i];
        if (i == 0) g_rowptr[0] = 0;
    }
}

__global__ void fill_kernel(const int* __restrict__ src, const int* __restrict__ dst,
                            const float* __restrict__ ew) {
    int e = blockIdx.x * blockDim.x + threadIdx.x;
    if (e >= ET) return;
    int s, d;
    float w;
    if (e < EE) { s = src[e]; d = dst[e]; w = ew[e]; }
    else        { s = d = e - EE; w = 1.0f; }
    int pos = atomicAdd(&g_cursor[d], 1);
    g_edge[pos] = make_int2(s, __float_as_int(w));   // single 8B scattered store
}

// ---------------- W1 pre-split: hi/lo TF32, interleaved [256][64hi|64lo] ----------
__global__ void convw1_kernel(const float* __restrict__ W) {
    int i = blockIdx.x * blockDim.x + threadIdx.x;
    if (i >= FIN * HID) return;
    int k = i >> 6, j = i & 63;
    float v = W[i];
    unsigned h = f2tf(v);
    g_W1hl[k * 128 + j]      = h;
    g_W1hl[k * 128 + 64 + j] = f2tf(v - __uint_as_float(h));
}

// ---------------- GEMM1: h1 = x @ W1, [NN,256]@[256,64], 3xTF32, cp.async ----------
// BM=128, BK=16, BN=64. 8 warps: wm 0..3 (32 rows), wn 0..1 (32 cols).
// A: raw floats cp.async'd, hi/lo split in-loop (once per fragment).
// B: pre-split hi/lo cp.async'd from g_W1hl — ZERO B conversions in the kernel.
// min 3 CTAs/SM via launch bounds. Fused epilogue: s1/d1 dot products.
__global__ __launch_bounds__(256, 3) void gemm1_tc(const float* __restrict__ X,
                                                   const float* __restrict__ A1S,
                                                   const float* __restrict__ A1D) {
    __shared__ float    As[2][128][20];   // stride 20: conflict-free frag LDS
    __shared__ unsigned Bs[2][16][136];   // stride 136: k*8+n covers all 32 banks
    __shared__ float    s_sm[2][128];
    __shared__ float    d_sm[2][128];

    const int t    = threadIdx.x;
    const int lane = t & 31;
    const int w    = t >> 5;
    const int wm   = w >> 1;
    const int wn   = w & 1;
    const int m0   = blockIdx.x * 128;

    // per-thread load coordinates
    const int ar0 = t >> 2,          ac0 = (t & 3) << 2;          // A chunk 0
    const int ar1 = (t + 256) >> 2,  ac1 = ((t + 256) & 3) << 2;  // A chunk 1
    const int br0 = t >> 5,          bq0 = (t & 31) << 2;         // B chunk 0 (rows 0-7)
    const int br1 = br0 + 8;                                      // B chunk 1 (rows 8-15)
    const int gr0 = m0 + ar0, gr1 = m0 + ar1;
    const bool ok0 = gr0 < NN, ok1 = gr1 < NN;

    auto load_tile = [&](int kc, int st) {
        cpa16(&As[st][ar0][ac0], X + (size_t)(ok0 ? gr0 : 0) * FIN + kc + ac0, ok0);
        cpa16(&As[st][ar1][ac1], X + (size_t)(ok1 ? gr1 : 0) * FIN + kc + ac1, ok1);
        cpa16(&Bs[st][br0][bq0], &g_W1hl[(kc + br0) * 128 + bq0], true);
        cpa16(&Bs[st][br1][bq0], &g_W1hl[(kc + br1) * 128 + bq0], true);
    };

    float acc[2][4][4];
    #pragma unroll
    for (int i = 0; i < 2; i++)
        #pragma unroll
        for (int j = 0; j < 4; j++)
            #pragma unroll
            for (int k = 0; k < 4; k++) acc[i][j][k] = 0.0f;

    load_tile(0, 0);
    cpa_commit();

    int cur = 0;
    for (int tile = 0; tile < 16; tile++) {
        if (tile < 15) {
            load_tile((tile + 1) * 16, cur ^ 1);
            cpa_commit();
            cpa_wait<1>();
        } else {
            cpa_wait<0>();
        }
        __syncthreads();

        #pragma unroll
        for (int ks = 0; ks < 2; ks++) {
            unsigned bh[4][2], bl[4][2];
            #pragma unroll
            for (int nt = 0; nt < 4; nt++) {
                int n = wn * 32 + nt * 8 + (lane >> 2);
                int k = ks * 8 + (lane & 3);
                bh[nt][0] = Bs[cur][k][n];          bh[nt][1] = Bs[cur][k + 4][n];
                bl[nt][0] = Bs[cur][k][64 + n];     bl[nt][1] = Bs[cur][k + 4][64 + n];
            }
            #pragma unroll
            for (int mt = 0; mt < 2; mt++) {
                int r = wm * 32 + mt * 16 + (lane >> 2);
                int c = ks * 8 + (lane & 3);
                float a0 = As[cur][r][c],     a1 = As[cur][r + 8][c];
                float a2 = As[cur][r][c + 4], a3 = As[cur][r + 8][c + 4];
                unsigned ah[4], al[4];
                ah[0] = f2tf(a0); al[0] = f2tf(a0 - __uint_as_float(ah[0]));
                ah[1] = f2tf(a1); al[1] = f2tf(a1 - __uint_as_float(ah[1]));
                ah[2] = f2tf(a2); al[2] = f2tf(a2 - __uint_as_float(ah[2]));
                ah[3] = f2tf(a3); al[3] = f2tf(a3 - __uint_as_float(ah[3]));
                #pragma unroll
                for (int nt = 0; nt < 4; nt++) {
                    mma_tf32(acc[mt][nt], ah, bh[nt]);
                    mma_tf32(acc[mt][nt], ah, bl[nt]);
                    mma_tf32(acc[mt][nt], al, bh[nt]);
                }
            }
        }
        __syncthreads();
        cur ^= 1;
    }

    // epilogue: store h1 + fused s/d dot products
    float a_s[8], a_d[8];
    #pragma unroll
    for (int nt = 0; nt < 4; nt++) {
        int c0 = wn * 32 + nt * 8 + (lane & 3) * 2;
        a_s[nt * 2]     = A1S[c0];
        a_s[nt * 2 + 1] = A1S[c0 + 1];
        a_d[nt * 2]     = A1D[c0];
        a_d[nt * 2 + 1] = A1D[c0 + 1];
    }

    #pragma unroll
    for (int mt = 0; mt < 2; mt++) {
        int r0 = m0 + wm * 32 + mt * 16 + (lane >> 2);
        float sp0 = 0.f, dp0 = 0.f, sp1 = 0.f, dp1 = 0.f;
        #pragma unroll
        for (int nt = 0; nt < 4; nt++) {
            int c0 = wn * 32 + nt * 8 + (lane & 3) * 2;
            if (r0 < NN)
                *(float2*)(g_h1 + (size_t)r0 * HID + c0) =
                    make_float2(acc[mt][nt][0], acc[mt][nt][1]);
            if (r0 + 8 < NN)
                *(float2*)(g_h1 + (size_t)(r0 + 8) * HID + c0) =
                    make_float2(acc[mt][nt][2], acc[mt][nt][3]);
            sp0 = fmaf(acc[mt][nt][0], a_s[nt * 2],     sp0);
            sp0 = fmaf(acc[mt][nt][1], a_s[nt * 2 + 1], sp0);
            sp1 = fmaf(acc[mt][nt][2], a_s[nt * 2],     sp1);
            sp1 = fmaf(acc[mt][nt][3], a_s[nt * 2 + 1], sp1);
            dp0 = fmaf(acc[mt][nt][0], a_d[nt * 2],     dp0);
            dp0 = fmaf(acc[mt][nt][1], a_d[nt * 2 + 1], dp0);
            dp1 = fmaf(acc[mt][nt][2], a_d[nt * 2],     dp1);
            dp1 = fmaf(acc[mt][nt][3], a_d[nt * 2 + 1], dp1);
        }
        #pragma unroll
        for (int off = 1; off < 4; off <<= 1) {
            sp0 += __shfl_xor_sync(0xffffffffu, sp0, off);
            sp1 += __shfl_xor_sync(0xffffffffu, sp1, off);
            dp0 += __shfl_xor_sync(0xffffffffu, dp0, off);
            dp1 += __shfl_xor_sync(0xffffffffu, dp1, off);
        }
        if ((lane & 3) == 0) {
            int lr = wm * 32 + mt * 16 + (lane >> 2);
            s_sm[wn][lr]     = sp0;
            s_sm[wn][lr + 8] = sp1;
            d_sm[wn][lr]     = dp0;
            d_sm[wn][lr + 8] = dp1;
        }
    }
    __syncthreads();
    if (t < 128) {
        int gr = m0 + t;
        if (gr < NN) {
            g_s1[gr] = s_sm[0][t] + s_sm[1][t];
            g_d1[gr] = d_sm[0][t] + d_sm[1][t];
        }
    }
}

// ---------------- GEMM2: h2 = out1 @ W2 (out1 already relu'd), fused s2/d2 ----------
__global__ __launch_bounds__(320) void gemm2_kernel(const float* __restrict__ W2,
                                                    const float* __restrict__ A2S,
                                                    const float* __restrict__ A2D) {
    __shared__ float hs[64][65];
    __shared__ unsigned long long ws2[64][20];
    __shared__ float s_sm2[10][64];
    __shared__ float d_sm2[10][64];
    const int t  = threadIdx.x;              // 320 threads
    const int tx = t % 10;
    const int ty = t / 10;
    const int m0 = blockIdx.x * 64;

    for (int idx = t; idx < 64 * 64; idx += 320) {
        int r = idx >> 6, c = idx & 63;
        int gr = m0 + r;
        hs[r][c] = (gr < NN) ? g_out1[(size_t)gr * HID + c] : 0.0f;
    }
    for (int idx = t; idx < 64 * 20; idx += 320) {
        int r = idx / 20, j = idx % 20;
        float2 v = *(const float2*)(W2 + (size_t)r * NC + j * 2);
        ws2[r][j] = pk2(v.x, v.y);
    }
    __syncthreads();

    if (ty < 32) {
        unsigned long long acc[2][2] = {{0ull, 0ull}, {0ull, 0ull}};
        #pragma unroll
        for (int k = 0; k < 64; k++) {
            unsigned long long b0 = ws2[k][tx * 2];
            unsigned long long b1 = ws2[k][tx * 2 + 1];
            #pragma unroll
            for (int i = 0; i < 2; i++) {
                float a = hs[ty * 2 + i][k];
                unsigned long long aa = pk2(a, a);
                acc[i][0] = ffma2(aa, b0, acc[i][0]);
                acc[i][1] = ffma2(aa, b1, acc[i][1]);
            }
        }
        float as0 = A2S[tx * 4], as1 = A2S[tx * 4 + 1], as2 = A2S[tx * 4 + 2], as3 = A2S[tx * 4 + 3];
        float ad0 = A2D[tx * 4], ad1 = A2D[tx * 4 + 1], ad2 = A2D[tx * 4 + 2], ad3 = A2D[tx * 4 + 3];
        #pragma unroll
        for (int i = 0; i < 2; i++) {
            int row = m0 + ty * 2 + i;
            float2 lo = upk2(acc[i][0]);
            float2 hi = upk2(acc[i][1]);
            if (row < NN) {
                float4 v = make_float4(lo.x, lo.y, hi.x, hi.y);
                *(float4*)(g_h2 + (size_t)row * NC + tx * 4) = v;
            }
            s_sm2[tx][ty * 2 + i] = lo.x * as0 + lo.y * as1 + hi.x * as2 + hi.y * as3;
            d_sm2[tx][ty * 2 + i] = lo.x * ad0 + lo.y * ad1 + hi.x * ad2 + hi.y * ad3;
        }
    }
    __syncthreads();
    if (t < 64) {
        int gr = m0 + t;
        if (gr < NN) {
            float ss = 0.f, dd = 0.f;
            #pragma unroll
            for (int j = 0; j < 10; j++) { ss += s_sm2[j][t]; dd += d_sm2[j][t]; }
            g_s2[gr] = ss;
            g_d2[gr] = dd;
        }
    }
}

// ---------------- aggregation: warp per dst node, fused pass, MLP=4 ----------------
// Packed int2 edge list: one 8B load per edge. Inactive lanes carry (w=0, src=0) so
// the x4-unrolled broadcast loop needs no guards.
template <int D, bool RELU>
__global__ __launch_bounds__(256) void agg_kernel(const float* __restrict__ H,
                                                  const float* __restrict__ S,
                                                  const float* __restrict__ DA,
                                                  float* __restrict__ OUT) {
    int v    = (blockIdx.x * blockDim.x + threadIdx.x) >> 5;
    int lane = threadIdx.x & 31;
    if (v >= NN) return;
    int p0 = g_rowptr[v], p1 = g_rowptr[v + 1];
    float dv = DA[v];

    int col = lane * 2;
    if (col > D - 2) col = D - 2;   // clamp (D=40: lanes 20..31 duplicate, don't store)

    float2 acc = make_float2(0.0f, 0.0f);
    float denom = 0.0f;

    for (int base = p0; base < p1; base += 32) {
        int p = base + lane;
        float wl = 0.0f;
        int   svl = 0;
        if (p < p1) {
            int2 e = g_edge[p];
            svl = e.x;
            float sc = S[svl] + dv;
            sc = sc > 0.0f ? sc : 0.2f * sc;
            float el = __expf(sc);
            denom += el;                               // denominator: exp only (no ew)
            wl = el * __int_as_float(e.y);             // numerator weight: exp * ew
        }
        int nj  = p1 - base; if (nj > 32) nj = 32;
        int njp = (nj + 3) & ~3;             // pad: extra lanes have w=0, src=0
        for (int j = 0; j < njp; j += 4) {
            float w0 = __shfl_sync(0xffffffffu, wl, j);
            float w1 = __shfl_sync(0xffffffffu, wl, j + 1);
            float w2 = __shfl_sync(0xffffffffu, wl, j + 2);
            float w3 = __shfl_sync(0xffffffffu, wl, j + 3);
            int   s0 = __shfl_sync(0xffffffffu, svl, j);
            int   s1 = __shfl_sync(0xffffffffu, svl, j + 1);
            int   s2 = __shfl_sync(0xffffffffu, svl, j + 2);
            int   s3 = __shfl_sync(0xffffffffu, svl, j + 3);
            float2 h0 = *(const float2*)(H + (size_t)s0 * D + col);
            float2 h1 = *(const float2*)(H + (size_t)s1 * D + col);
            float2 h2 = *(const float2*)(H + (size_t)s2 * D + col);
            float2 h3 = *(const float2*)(H + (size_t)s3 * D + col);
            acc.x = fmaf(w0, h0.x, acc.x);  acc.y = fmaf(w0, h0.y, acc.y);
            acc.x = fmaf(w1, h1.x, acc.x);  acc.y = fmaf(w1, h1.y, acc.y);
            acc.x = fmaf(w2, h2.x, acc.x);  acc.y = fmaf(w2, h2.y, acc.y);
            acc.x = fmaf(w3, h3.x, acc.x);  acc.y = fmaf(w3, h3.y, acc.y);
        }
    }
    #pragma unroll
    for (int off = 16; off; off >>= 1)
        denom += __shfl_xor_sync(0xffffffffu, denom, off);
    float inv = 1.0f / denom;   // >0 guaranteed: every node has a self loop

    if (lane * 2 < D) {
        float ox = acc.x * inv, oy = acc.y * inv;
        if (RELU) { ox = ox > 0.f ? ox : 0.f; oy = oy > 0.f ? oy : 0.f; }
        *(float2*)(OUT + (size_t)v * D + col) = make_float2(ox, oy);
    }
}

// ---------------- launch ----------------
extern "C" void kernel_launch(void* const* d_in, const int* in_sizes, int n_in,
                              void* d_out, int out_size) {
    const float* x   = (const float*)d_in[0];
    const int*   ei  = (const int*)  d_in[1];
    const float* ew  = (const float*)d_in[2];
    const float* W1  = (const float*)d_in[3];
    const float* a1s = (const float*)d_in[4];
    const float* a1d = (const float*)d_in[5];
    const float* W2  = (const float*)d_in[6];
    const float* a2s = (const float*)d_in[7];
    const float* a2d = (const float*)d_in[8];
    float* out = (float*)d_out;

    const int* srcA = ei;
    const int* dstA = ei + EE;

    float *ph1, *pout1, *ph2, *ps1, *pd1, *ps2, *pd2;
    cudaGetSymbolAddress((void**)&ph1,   g_h1);
    cudaGetSymbolAddress((void**)&pout1, g_out1);
    cudaGetSymbolAddress((void**)&ph2,   g_h2);
    cudaGetSymbolAddress((void**)&ps1,   g_s1);
    cudaGetSymbolAddress((void**)&pd1,   g_d1);
    cudaGetSymbolAddress((void**)&ps2,   g_s2);
    cudaGetSymbolAddress((void**)&pd2,   g_d2);

    // Capture-safe side stream + fork/join events
    static cudaStream_t s2 = nullptr;
    static cudaEvent_t  evF = nullptr, evJ = nullptr;
    if (!s2) {
        cudaStreamCreateWithFlags(&s2, cudaStreamNonBlocking);
        cudaEventCreateWithFlags(&evF, cudaEventDisableTiming);
        cudaEventCreateWithFlags(&evJ, cudaEventDisableTiming);
    }

    const int TPB = 256;
    const int nb  = (NN + 1023) / 1024;

    // Fork: CSR build on side stream; W1 pre-split + gemm1 on main stream
    cudaEventRecord(evF, 0);
    cudaStreamWaitEvent(s2, evF, 0);
    zero_cnt_kernel<<<(NN + TPB - 1) / TPB, TPB, 0, s2>>>();
    hist_kernel<<<(ET + TPB - 1) / TPB, TPB, 0, s2>>>(dstA);
    scan1_kernel<<<nb, 1024, 0, s2>>>();
    convw1_kernel<<<(FIN * HID + TPB - 1) / TPB, TPB>>>(W1);    // main stream, tiny
    gemm1_tc<<<(NN + 127) / 128, 256>>>(x, a1s, a1d);           // main stream
    scan23_kernel<<<nb, 1024, 0, s2>>>(nb);
    fill_kernel<<<(ET + TPB - 1) / TPB, TPB, 0, s2>>>(srcA, dstA, ew);
    cudaEventRecord(evJ, s2);

    // Join, then the serial tail
    cudaStreamWaitEvent(0, evJ, 0);
    agg_kernel<HID, true><<<(NN * 32 + TPB - 1) / TPB, TPB>>>(ph1, ps1, pd1, pout1);
    gemm2_kernel<<<(NN + 63) / 64, 320>>>(W2, a2s, a2d);
    agg_kernel<NC, false><<<(NN * 32 + TPB - 1) / TPB, TPB>>>(ph2, ps2, pd2, out);
}

// round 13
// speedup vs baseline: 1.1543x; 1.0270x over previous
#include <cuda_runtime.h>
#include <cuda_bf16.h>
#include <cuda_fp16.h>

// Problem constants (fixed shapes for GAT_68762426409265)
#define NN  100000          // nodes
#define FIN 256             // input features
#define HID 64              // hidden
#define NC  40              // classes
#define EE  1600000         // edges (without self loops)
#define ET  (EE + NN)       // edges + self loops

// ---------------- device scratch (static, no allocation) ----------------
__device__ unsigned g_h1h[(size_t)NN * (HID / 2)];  // layer1 projection, packed half2
__device__ float    g_out1[(size_t)NN * HID];       // layer1 aggregated (relu'd), fp32
__device__ unsigned g_h2h[(size_t)NN * (NC / 2)];   // layer2 projection, packed half2
__device__ float    g_s1[NN];
__device__ float    g_d1[NN];
__device__ float    g_s2[NN];
__device__ float    g_d2[NN];
__device__ int      g_cnt[NN];
__device__ int      g_scan[NN];
__device__ int      g_rowptr[NN + 1];
__device__ int      g_cursor[NN];
__device__ int      g_bsum[128];
__device__ int2     g_edge[ET];                 // packed {src, ew-bits}
__device__ unsigned g_W1hl[FIN * 128];          // W1 pre-split: row k = [64 hi | 64 lo]

// ---------------- small asm helpers ----------------
__device__ __forceinline__ unsigned f2tf(float x) {
    unsigned r; asm("cvt.rna.tf32.f32 %0, %1;" : "=r"(r) : "f"(x)); return r;
}
__device__ __forceinline__ void mma_tf32(float* c, const unsigned* a, const unsigned* b) {
    asm volatile("mma.sync.aligned.m16n8k8.row.col.f32.tf32.tf32.f32 "
                 "{%0,%1,%2,%3}, {%4,%5,%6,%7}, {%8,%9}, {%0,%1,%2,%3};"
                 : "+f"(c[0]), "+f"(c[1]), "+f"(c[2]), "+f"(c[3])
                 : "r"(a[0]), "r"(a[1]), "r"(a[2]), "r"(a[3]),
                   "r"(b[0]), "r"(b[1]));
}
__device__ __forceinline__ unsigned long long pk2(float x, float y) {
    unsigned long long r;
    asm("mov.b64 %0, {%1,%2};" : "=l"(r) : "f"(x), "f"(y));
    return r;
}
__device__ __forceinline__ float2 upk2(unsigned long long v) {
    float x, y;
    asm("mov.b64 {%0,%1}, %2;" : "=f"(x), "=f"(y) : "l"(v));
    return make_float2(x, y);
}
__device__ __forceinline__ unsigned long long ffma2(unsigned long long a,
                                                    unsigned long long b,
                                                    unsigned long long c) {
    unsigned long long d;
    asm("fma.rn.f32x2 %0, %1, %2, %3;" : "=l"(d) : "l"(a), "l"(b), "l"(c));
    return d;
}
__device__ __forceinline__ unsigned pkh2(float lo, float hi) {
    unsigned r;
    asm("cvt.rn.f16x2.f32 %0, %1, %2;" : "=r"(r) : "f"(hi), "f"(lo));
    return r;
}
__device__ __forceinline__ float2 uph2(unsigned u) {
    __half2 h = *reinterpret_cast<__half2*>(&u);
    return __half22float2(h);
}
__device__ __forceinline__ void cpa16(void* dst_smem, const void* src, bool pred) {
    unsigned d = (unsigned)__cvta_generic_to_shared(dst_smem);
    int sz = pred ? 16 : 0;   // src-size 0 => zero-fill
    asm volatile("cp.async.cg.shared.global [%0], [%1], 16, %2;\n"
                 :: "r"(d), "l"(src), "r"(sz));
}
__device__ __forceinline__ void cpa_commit() {
    asm volatile("cp.async.commit_group;\n" ::: "memory");
}
template <int N>
__device__ __forceinline__ void cpa_wait() {
    asm volatile("cp.async.wait_group %0;\n" :: "n"(N) : "memory");
}

// ---------------- CSR build ----------------
__global__ void zero_cnt_kernel() {
    int i = blockIdx.x * blockDim.x + threadIdx.x;
    if (i < NN) g_cnt[i] = 0;
}

__global__ void hist_kernel(const int* __restrict__ dst) {
    int e = blockIdx.x * blockDim.x + threadIdx.x;
    if (e >= ET) return;
    int d = (e < EE) ? dst[e] : (e - EE);
    atomicAdd(&g_cnt[d], 1);
}

__global__ void scan1_kernel() {
    __shared__ int tmp[1024];
    int t = threadIdx.x;
    int i = blockIdx.x * 1024 + t;
    tmp[t] = (i < NN) ? g_cnt[i] : 0;
    __syncthreads();
    #pragma unroll
    for (int off = 1; off < 1024; off <<= 1) {
        int x = 0;
        if (t >= off) x = tmp[t - off];
        __syncthreads();
        tmp[t] += x;
        __syncthreads();
    }
    if (i < NN) g_scan[i] = tmp[t];
    if (t == 1023) g_bsum[blockIdx.x] = tmp[1023];
}

// Fused scan2 + scan3 + cursor
__global__ void scan23_kernel(int nb) {
    __shared__ int bs[128];
    int t = threadIdx.x;
    if (t < 128) bs[t] = (t < nb) ? g_bsum[t] : 0;
    __syncthreads();
    #pragma unroll
    for (int off = 1; off < 128; off <<= 1) {
        int x = 0;
        if (t < 128 && t >= off) x = bs[t - off];
        __syncthreads();
        if (t < 128) bs[t] += x;
        __syncthreads();
    }
    int i = blockIdx.x * 1024 + t;
    if (i < NN) {
        int blk  = i >> 10;
        int boff = blk ? bs[blk - 1] : 0;
        int inc  = g_scan[i] + boff;
        g_rowptr[i + 1] = inc;
        g_cursor[i]     = inc - g_cnt[i];
        if (i == 0) g_rowptr[0] = 0;
    }
}

__global__ void fill_kernel(const int* __restrict__ src, const int* __restrict__ dst,
                            const float* __restrict__ ew) {
    int e = blockIdx.x * blockDim.x + threadIdx.x;
    if (e >= ET) return;
    int s, d;
    float w;
    if (e < EE) { s = src[e]; d = dst[e]; w = ew[e]; }
    else        { s = d = e - EE; w = 1.0f; }
    int pos = atomicAdd(&g_cursor[d], 1);
    g_edge[pos] = make_int2(s, __float_as_int(w));   // single 8B scattered store
}

// ---------------- W1 pre-split: hi/lo TF32, interleaved [256][64hi|64lo] ----------
__global__ void convw1_kernel(const float* __restrict__ W) {
    int i = blockIdx.x * blockDim.x + threadIdx.x;
    if (i >= FIN * HID) return;
    int k = i >> 6, j = i & 63;
    float v = W[i];
    unsigned h = f2tf(v);
    g_W1hl[k * 128 + j]      = h;
    g_W1hl[k * 128 + 64 + j] = f2tf(v - __uint_as_float(h));
}

// ---------------- GEMM1: h1 = x @ W1, [NN,256]@[256,64], 3xTF32, cp.async ----------
// BM=128, BK=16, BN=64. 8 warps: wm 0..3 (32 rows), wn 0..1 (32 cols).
// A: raw floats cp.async'd, hi/lo split in-loop. B: pre-split hi/lo from g_W1hl.
// h1 stored as packed half2 (fp32 accs kept for the s/d epilogue dot products).
__global__ __launch_bounds__(256, 3) void gemm1_tc(const float* __restrict__ X,
                                                   const float* __restrict__ A1S,
                                                   const float* __restrict__ A1D) {
    __shared__ float    As[2][128][20];   // stride 20: conflict-free frag LDS
    __shared__ unsigned Bs[2][16][136];   // stride 136: k*8+n covers all 32 banks
    __shared__ float    s_sm[2][128];
    __shared__ float    d_sm[2][128];

    const int t    = threadIdx.x;
    const int lane = t & 31;
    const int w    = t >> 5;
    const int wm   = w >> 1;
    const int wn   = w & 1;
    const int m0   = blockIdx.x * 128;

    // per-thread load coordinates
    const int ar0 = t >> 2,          ac0 = (t & 3) << 2;          // A chunk 0
    const int ar1 = (t + 256) >> 2,  ac1 = ((t + 256) & 3) << 2;  // A chunk 1
    const int br0 = t >> 5,          bq0 = (t & 31) << 2;         // B chunk 0 (rows 0-7)
    const int br1 = br0 + 8;                                      // B chunk 1 (rows 8-15)
    const int gr0 = m0 + ar0, gr1 = m0 + ar1;
    const bool ok0 = gr0 < NN, ok1 = gr1 < NN;

    auto load_tile = [&](int kc, int st) {
        cpa16(&As[st][ar0][ac0], X + (size_t)(ok0 ? gr0 : 0) * FIN + kc + ac0, ok0);
        cpa16(&As[st][ar1][ac1], X + (size_t)(ok1 ? gr1 : 0) * FIN + kc + ac1, ok1);
        cpa16(&Bs[st][br0][bq0], &g_W1hl[(kc + br0) * 128 + bq0], true);
        cpa16(&Bs[st][br1][bq0], &g_W1hl[(kc + br1) * 128 + bq0], true);
    };

    float acc[2][4][4];
    #pragma unroll
    for (int i = 0; i < 2; i++)
        #pragma unroll
        for (int j = 0; j < 4; j++)
            #pragma unroll
            for (int k = 0; k < 4; k++) acc[i][j][k] = 0.0f;

    load_tile(0, 0);
    cpa_commit();

    int cur = 0;
    for (int tile = 0; tile < 16; tile++) {
        if (tile < 15) {
            load_tile((tile + 1) * 16, cur ^ 1);
            cpa_commit();
            cpa_wait<1>();
        } else {
            cpa_wait<0>();
        }
        __syncthreads();

        #pragma unroll
        for (int ks = 0; ks < 2; ks++) {
            unsigned bh[4][2], bl[4][2];
            #pragma unroll
            for (int nt = 0; nt < 4; nt++) {
                int n = wn * 32 + nt * 8 + (lane >> 2);
                int k = ks * 8 + (lane & 3);
                bh[nt][0] = Bs[cur][k][n];          bh[nt][1] = Bs[cur][k + 4][n];
                bl[nt][0] = Bs[cur][k][64 + n];     bl[nt][1] = Bs[cur][k + 4][64 + n];
            }
            #pragma unroll
            for (int mt = 0; mt < 2; mt++) {
                int r = wm * 32 + mt * 16 + (lane >> 2);
                int c = ks * 8 + (lane & 3);
                float a0 = As[cur][r][c],     a1 = As[cur][r + 8][c];
                float a2 = As[cur][r][c + 4], a3 = As[cur][r + 8][c + 4];
                unsigned ah[4], al[4];
                ah[0] = f2tf(a0); al[0] = f2tf(a0 - __uint_as_float(ah[0]));
                ah[1] = f2tf(a1); al[1] = f2tf(a1 - __uint_as_float(ah[1]));
                ah[2] = f2tf(a2); al[2] = f2tf(a2 - __uint_as_float(ah[2]));
                ah[3] = f2tf(a3); al[3] = f2tf(a3 - __uint_as_float(ah[3]));
                #pragma unroll
                for (int nt = 0; nt < 4; nt++) {
                    mma_tf32(acc[mt][nt], ah, bh[nt]);
                    mma_tf32(acc[mt][nt], ah, bl[nt]);
                    mma_tf32(acc[mt][nt], al, bh[nt]);
                }
            }
        }
        __syncthreads();
        cur ^= 1;
    }

    // epilogue: store h1 (half2) + fused s/d dot products (from fp32 accs)
    float a_s[8], a_d[8];
    #pragma unroll
    for (int nt = 0; nt < 4; nt++) {
        int c0 = wn * 32 + nt * 8 + (lane & 3) * 2;
        a_s[nt * 2]     = A1S[c0];
        a_s[nt * 2 + 1] = A1S[c0 + 1];
        a_d[nt * 2]     = A1D[c0];
        a_d[nt * 2 + 1] = A1D[c0 + 1];
    }

    #pragma unroll
    for (int mt = 0; mt < 2; mt++) {
        int r0 = m0 + wm * 32 + mt * 16 + (lane >> 2);
        float sp0 = 0.f, dp0 = 0.f, sp1 = 0.f, dp1 = 0.f;
        #pragma unroll
        for (int nt = 0; nt < 4; nt++) {
            int cp = wn * 16 + nt * 4 + (lane & 3);   // half2 column index
            if (r0 < NN)
                g_h1h[(size_t)r0 * 32 + cp] = pkh2(acc[mt][nt][0], acc[mt][nt][1]);
            if (r0 + 8 < NN)
                g_h1h[(size_t)(r0 + 8) * 32 + cp] = pkh2(acc[mt][nt][2], acc[mt][nt][3]);
            sp0 = fmaf(acc[mt][nt][0], a_s[nt * 2],     sp0);
            sp0 = fmaf(acc[mt][nt][1], a_s[nt * 2 + 1], sp0);
            sp1 = fmaf(acc[mt][nt][2], a_s[nt * 2],     sp1);
            sp1 = fmaf(acc[mt][nt][3], a_s[nt * 2 + 1], sp1);
            dp0 = fmaf(acc[mt][nt][0], a_d[nt * 2],     dp0);
            dp0 = fmaf(acc[mt][nt][1], a_d[nt * 2 + 1], dp0);
            dp1 = fmaf(acc[mt][nt][2], a_d[nt * 2],     dp1);
            dp1 = fmaf(acc[mt][nt][3], a_d[nt * 2 + 1], dp1);
        }
        #pragma unroll
        for (int off = 1; off < 4; off <<= 1) {
            sp0 += __shfl_xor_sync(0xffffffffu, sp0, off);
            sp1 += __shfl_xor_sync(0xffffffffu, sp1, off);
            dp0 += __shfl_xor_sync(0xffffffffu, dp0, off);
            dp1 += __shfl_xor_sync(0xffffffffu, dp1, off);
        }
        if ((lane & 3) == 0) {
            int lr = wm * 32 + mt * 16 + (lane >> 2);
            s_sm[wn][lr]     = sp0;
            s_sm[wn][lr + 8] = sp1;
            d_sm[wn][lr]     = dp0;
            d_sm[wn][lr + 8] = dp1;
        }
    }
    __syncthreads();
    if (t < 128) {
        int gr = m0 + t;
        if (gr < NN) {
            g_s1[gr] = s_sm[0][t] + s_sm[1][t];
            g_d1[gr] = d_sm[0][t] + d_sm[1][t];
        }
    }
}

// ---------------- GEMM2: h2 = out1 @ W2 (out1 already relu'd), fused s2/d2 ----------
// h2 stored as packed half2; s2/d2 from fp32 accumulators.
__global__ __launch_bounds__(320) void gemm2_kernel(const float* __restrict__ W2,
                                                    const float* __restrict__ A2S,
                                                    const float* __restrict__ A2D) {
    __shared__ float hs[64][65];
    __shared__ unsigned long long ws2[64][20];
    __shared__ float s_sm2[10][64];
    __shared__ float d_sm2[10][64];
    const int t  = threadIdx.x;              // 320 threads
    const int tx = t % 10;
    const int ty = t / 10;
    const int m0 = blockIdx.x * 64;

    for (int idx = t; idx < 64 * 64; idx += 320) {
        int r = idx >> 6, c = idx & 63;
        int gr = m0 + r;
        hs[r][c] = (gr < NN) ? g_out1[(size_t)gr * HID + c] : 0.0f;
    }
    for (int idx = t; idx < 64 * 20; idx += 320) {
        int r = idx / 20, j = idx % 20;
        float2 v = *(const float2*)(W2 + (size_t)r * NC + j * 2);
        ws2[r][j] = pk2(v.x, v.y);
    }
    __syncthreads();

    if (ty < 32) {
        unsigned long long acc[2][2] = {{0ull, 0ull}, {0ull, 0ull}};
        #pragma unroll
        for (int k = 0; k < 64; k++) {
            unsigned long long b0 = ws2[k][tx * 2];
            unsigned long long b1 = ws2[k][tx * 2 + 1];
            #pragma unroll
            for (int i = 0; i < 2; i++) {
                float a = hs[ty * 2 + i][k];
                unsigned long long aa = pk2(a, a);
                acc[i][0] = ffma2(aa, b0, acc[i][0]);
                acc[i][1] = ffma2(aa, b1, acc[i][1]);
            }
        }
        float as0 = A2S[tx * 4], as1 = A2S[tx * 4 + 1], as2 = A2S[tx * 4 + 2], as3 = A2S[tx * 4 + 3];
        float ad0 = A2D[tx * 4], ad1 = A2D[tx * 4 + 1], ad2 = A2D[tx * 4 + 2], ad3 = A2D[tx * 4 + 3];
        #pragma unroll
        for (int i = 0; i < 2; i++) {
            int row = m0 + ty * 2 + i;
            float2 lo = upk2(acc[i][0]);
            float2 hi = upk2(acc[i][1]);
            if (row < NN) {
                uint2 hv = make_uint2(pkh2(lo.x, lo.y), pkh2(hi.x, hi.y));
                *(uint2*)(g_h2h + (size_t)row * 20 + tx * 2) = hv;
            }
            s_sm2[tx][ty * 2 + i] = lo.x * as0 + lo.y * as1 + hi.x * as2 + hi.y * as3;
            d_sm2[tx][ty * 2 + i] = lo.x * ad0 + lo.y * ad1 + hi.x * ad2 + hi.y * ad3;
        }
    }
    __syncthreads();
    if (t < 64) {
        int gr = m0 + t;
        if (gr < NN) {
            float ss = 0.f, dd = 0.f;
            #pragma unroll
            for (int j = 0; j < 10; j++) { ss += s_sm2[j][t]; dd += d_sm2[j][t]; }
            g_s2[gr] = ss;
            g_d2[gr] = dd;
        }
    }
}

// ---------------- aggregation: warp per dst node, fused pass, MLP=4, half2 H --------
// H rows are packed half2 (D/2 words). Lane covers 2 feature cols = one 4B load/edge.
// fp32 accumulation throughout; only the gathered features are fp16.
template <int D, bool RELU>
__global__ __launch_bounds__(256) void agg_kernel(const unsigned* __restrict__ H,
                                                  const float* __restrict__ S,
                                                  const float* __restrict__ DA,
                                                  float* __restrict__ OUT) {
    constexpr int DH = D / 2;
    int v    = (blockIdx.x * blockDim.x + threadIdx.x) >> 5;
    int lane = threadIdx.x & 31;
    if (v >= NN) return;
    int p0 = g_rowptr[v], p1 = g_rowptr[v + 1];
    float dv = DA[v];

    int cp = lane < DH ? lane : DH - 1;   // clamp (D=40: lanes 20..31 duplicate)

    float2 acc = make_float2(0.0f, 0.0f);
    float denom = 0.0f;

    for (int base = p0; base < p1; base += 32) {
        int p = base + lane;
        float wl = 0.0f;
        int   svl = 0;
        if (p < p1) {
            int2 e = g_edge[p];
            svl = e.x;
            float sc = S[svl] + dv;
            sc = sc > 0.0f ? sc : 0.2f * sc;
            float el = __expf(sc);
            denom += el;                               // denominator: exp only (no ew)
            wl = el * __int_as_float(e.y);             // numerator weight: exp * ew
        }
        int nj  = p1 - base; if (nj > 32) nj = 32;
        int njp = (nj + 3) & ~3;             // pad: extra lanes have w=0, src=0
        for (int j = 0; j < njp; j += 4) {
            float w0 = __shfl_sync(0xffffffffu, wl, j);
            float w1 = __shfl_sync(0xffffffffu, wl, j + 1);
            float w2 = __shfl_sync(0xffffffffu, wl, j + 2);
            float w3 = __shfl_sync(0xffffffffu, wl, j + 3);
            int   s0 = __shfl_sync(0xffffffffu, svl, j);
            int   s1 = __shfl_sync(0xffffffffu, svl, j + 1);
            int   s2 = __shfl_sync(0xffffffffu, svl, j + 2);
            int   s3 = __shfl_sync(0xffffffffu, svl, j + 3);
            float2 h0 = uph2(H[(size_t)s0 * DH + cp]);
            float2 h1 = uph2(H[(size_t)s1 * DH + cp]);
            float2 h2 = uph2(H[(size_t)s2 * DH + cp]);
            float2 h3 = uph2(H[(size_t)s3 * DH + cp]);
            acc.x = fmaf(w0, h0.x, acc.x);  acc.y = fmaf(w0, h0.y, acc.y);
            acc.x = fmaf(w1, h1.x, acc.x);  acc.y = fmaf(w1, h1.y, acc.y);
            acc.x = fmaf(w2, h2.x, acc.x);  acc.y = fmaf(w2, h2.y, acc.y);
            acc.x = fmaf(w3, h3.x, acc.x);  acc.y = fmaf(w3, h3.y, acc.y);
        }
    }
    #pragma unroll
    for (int off = 16; off; off >>= 1)
        denom += __shfl_xor_sync(0xffffffffu, denom, off);
    float inv = 1.0f / denom;   // >0 guaranteed: every node has a self loop

    if (lane < DH) {
        float ox = acc.x * inv, oy = acc.y * inv;
        if (RELU) { ox = ox > 0.f ? ox : 0.f; oy = oy > 0.f ? oy : 0.f; }
        *(float2*)(OUT + (size_t)v * D + lane * 2) = make_float2(ox, oy);
    }
}

// ---------------- launch ----------------
extern "C" void kernel_launch(void* const* d_in, const int* in_sizes, int n_in,
                              void* d_out, int out_size) {
    const float* x   = (const float*)d_in[0];
    const int*   ei  = (const int*)  d_in[1];
    const float* ew  = (const float*)d_in[2];
    const float* W1  = (const float*)d_in[3];
    const float* a1s = (const float*)d_in[4];
    const float* a1d = (const float*)d_in[5];
    const float* W2  = (const float*)d_in[6];
    const float* a2s = (const float*)d_in[7];
    const float* a2d = (const float*)d_in[8];
    float* out = (float*)d_out;

    const int* srcA = ei;
    const int* dstA = ei + EE;

    unsigned *ph1h, *ph2h;
    float *pout1, *ps1, *pd1, *ps2, *pd2;
    cudaGetSymbolAddress((void**)&ph1h,  g_h1h);
    cudaGetSymbolAddress((void**)&pout1, g_out1);
    cudaGetSymbolAddress((void**)&ph2h,  g_h2h);
    cudaGetSymbolAddress((void**)&ps1,   g_s1);
    cudaGetSymbolAddress((void**)&pd1,   g_d1);
    cudaGetSymbolAddress((void**)&ps2,   g_s2);
    cudaGetSymbolAddress((void**)&pd2,   g_d2);

    // Capture-safe side stream + fork/join events
    static cudaStream_t s2 = nullptr;
    static cudaEvent_t  evF = nullptr, evJ = nullptr;
    if (!s2) {
        cudaStreamCreateWithFlags(&s2, cudaStreamNonBlocking);
        cudaEventCreateWithFlags(&evF, cudaEventDisableTiming);
        cudaEventCreateWithFlags(&evJ, cudaEventDisableTiming);
    }

    const int TPB = 256;
    const int nb  = (NN + 1023) / 1024;

    // Fork: CSR build on side stream; W1 pre-split + gemm1 on main stream
    cudaEventRecord(evF, 0);
    cudaStreamWaitEvent(s2, evF, 0);
    zero_cnt_kernel<<<(NN + TPB - 1) / TPB, TPB, 0, s2>>>();
    hist_kernel<<<(ET + TPB - 1) / TPB, TPB, 0, s2>>>(dstA);
    scan1_kernel<<<nb, 1024, 0, s2>>>();
    convw1_kernel<<<(FIN * HID + TPB - 1) / TPB, TPB>>>(W1);    // main stream, tiny
    gemm1_tc<<<(NN + 127) / 128, 256>>>(x, a1s, a1d);           // main stream
    scan23_kernel<<<nb, 1024, 0, s2>>>(nb);
    fill_kernel<<<(ET + TPB - 1) / TPB, TPB, 0, s2>>>(srcA, dstA, ew);
    cudaEventRecord(evJ, s2);

    // Join, then the serial tail
    cudaStreamWaitEvent(0, evJ, 0);
    agg_kernel<HID, true><<<(NN * 32 + TPB - 1) / TPB, TPB>>>(ph1h, ps1, pd1, pout1);
    gemm2_kernel<<<(NN + 63) / 64, 320>>>(W2, a2s, a2d);
    agg_kernel<NC, false><<<(NN * 32 + TPB - 1) / TPB, TPB>>>(ph2h, ps2, pd2, out);
}

// round 16
// speedup vs baseline: 1.2523x; 1.0849x over previous
#include <cuda_runtime.h>
#include <cuda_bf16.h>
#include <cuda_fp16.h>

// Problem constants (fixed shapes for GAT_68762426409265)
#define NN  100000          // nodes
#define FIN 256             // input features
#define HID 64              // hidden
#define NC  40              // classes
#define EE  1600000         // edges (without self loops)
#define ET  (EE + NN)       // edges + self loops

// ---------------- device scratch (static, no allocation) ----------------
__device__ unsigned g_h1h[(size_t)NN * (HID / 2)];  // layer1 projection, packed half2
__device__ float    g_out1[(size_t)NN * HID];       // layer1 aggregated (relu'd), fp32
__device__ unsigned g_h2h[(size_t)NN * (NC / 2)];   // layer2 projection, packed half2
__device__ float    g_s1[NN];
__device__ float    g_d1[NN];
__device__ float    g_s2[NN];
__device__ float    g_d2[NN];
__device__ int      g_cnt[NN];
__device__ int      g_scan[NN];
__device__ int      g_rowptr[NN + 1];
__device__ int      g_cursor[NN];
__device__ int      g_bsum[128];
__device__ int2     g_edge[ET];                 // packed {src, ew-bits}
__device__ unsigned g_W1hl[FIN * 128];          // W1 pre-split: row k = [64 hi | 64 lo]

// ---------------- small asm helpers ----------------
__device__ __forceinline__ unsigned f2tf(float x) {
    unsigned r; asm("cvt.rna.tf32.f32 %0, %1;" : "=r"(r) : "f"(x)); return r;
}
__device__ __forceinline__ void mma_tf32(float* c, const unsigned* a, const unsigned* b) {
    asm volatile("mma.sync.aligned.m16n8k8.row.col.f32.tf32.tf32.f32 "
                 "{%0,%1,%2,%3}, {%4,%5,%6,%7}, {%8,%9}, {%0,%1,%2,%3};"
                 : "+f"(c[0]), "+f"(c[1]), "+f"(c[2]), "+f"(c[3])
                 : "r"(a[0]), "r"(a[1]), "r"(a[2]), "r"(a[3]),
                   "r"(b[0]), "r"(b[1]));
}
__device__ __forceinline__ unsigned long long pk2(float x, float y) {
    unsigned long long r;
    asm("mov.b64 %0, {%1,%2};" : "=l"(r) : "f"(x), "f"(y));
    return r;
}
__device__ __forceinline__ float2 upk2(unsigned long long v) {
    float x, y;
    asm("mov.b64 {%0,%1}, %2;" : "=f"(x), "=f"(y) : "l"(v));
    return make_float2(x, y);
}
__device__ __forceinline__ unsigned long long ffma2(unsigned long long a,
                                                    unsigned long long b,
                                                    unsigned long long c) {
    unsigned long long d;
    asm("fma.rn.f32x2 %0, %1, %2, %3;" : "=l"(d) : "l"(a), "l"(b), "l"(c));
    return d;
}
__device__ __forceinline__ unsigned pkh2(float lo, float hi) {
    unsigned r;
    asm("cvt.rn.f16x2.f32 %0, %1, %2;" : "=r"(r) : "f"(hi), "f"(lo));
    return r;
}
__device__ __forceinline__ float2 uph2(unsigned u) {
    __half2 h = *reinterpret_cast<__half2*>(&u);
    return __half22float2(h);
}
__device__ __forceinline__ void cpa16(void* dst_smem, const void* src, bool pred) {
    unsigned d = (unsigned)__cvta_generic_to_shared(dst_smem);
    int sz = pred ? 16 : 0;   // src-size 0 => zero-fill
    asm volatile("cp.async.cg.shared.global [%0], [%1], 16, %2;\n"
                 :: "r"(d), "l"(src), "r"(sz));
}
__device__ __forceinline__ void cpa_commit() {
    asm volatile("cp.async.commit_group;\n" ::: "memory");
}
template <int N>
__device__ __forceinline__ void cpa_wait() {
    asm volatile("cp.async.wait_group %0;\n" :: "n"(N) : "memory");
}

// ---------------- CSR build ----------------
__global__ void zero_cnt_kernel() {
    int i = blockIdx.x * blockDim.x + threadIdx.x;
    if (i < NN) g_cnt[i] = 0;
}

__global__ void hist_kernel(const int* __restrict__ dst) {
    int e = blockIdx.x * blockDim.x + threadIdx.x;
    if (e >= ET) return;
    int d = (e < EE) ? dst[e] : (e - EE);
    atomicAdd(&g_cnt[d], 1);
}

__global__ void scan1_kernel() {
    __shared__ int tmp[1024];
    int t = threadIdx.x;
    int i = blockIdx.x * 1024 + t;
    tmp[t] = (i < NN) ? g_cnt[i] : 0;
    __syncthreads();
    #pragma unroll
    for (int off = 1; off < 1024; off <<= 1) {
        int x = 0;
        if (t >= off) x = tmp[t - off];
        __syncthreads();
        tmp[t] += x;
        __syncthreads();
    }
    if (i < NN) g_scan[i] = tmp[t];
    if (t == 1023) g_bsum[blockIdx.x] = tmp[1023];
}

// Fused scan2 + scan3 + cursor
__global__ void scan23_kernel(int nb) {
    __shared__ int bs[128];
    int t = threadIdx.x;
    if (t < 128) bs[t] = (t < nb) ? g_bsum[t] : 0;
    __syncthreads();
    #pragma unroll
    for (int off = 1; off < 128; off <<= 1) {
        int x = 0;
        if (t < 128 && t >= off) x = bs[t - off];
        __syncthreads();
        if (t < 128) bs[t] += x;
        __syncthreads();
    }
    int i = blockIdx.x * 1024 + t;
    if (i < NN) {
        int blk  = i >> 10;
        int boff = blk ? bs[blk - 1] : 0;
        int inc  = g_scan[i] + boff;
        g_rowptr[i + 1] = inc;
        g_cursor[i]     = inc - g_cnt[i];
        if (i == 0) g_rowptr[0] = 0;
    }
}

__global__ void fill_kernel(const int* __restrict__ src, const int* __restrict__ dst,
                            const float* __restrict__ ew) {
    int e = blockIdx.x * blockDim.x + threadIdx.x;
    if (e >= ET) return;
    int s, d;
    float w;
    if (e < EE) { s = src[e]; d = dst[e]; w = ew[e]; }
    else        { s = d = e - EE; w = 1.0f; }
    int pos = atomicAdd(&g_cursor[d], 1);
    g_edge[pos] = make_int2(s, __float_as_int(w));   // single 8B scattered store
}

// ---------------- W1 pre-split: hi/lo TF32, interleaved [256][64hi|64lo] ----------
__global__ void convw1_kernel(const float* __restrict__ W) {
    int i = blockIdx.x * blockDim.x + threadIdx.x;
    if (i >= FIN * HID) return;
    int k = i >> 6, j = i & 63;
    float v = W[i];
    unsigned h = f2tf(v);
    g_W1hl[k * 128 + j]      = h;
    g_W1hl[k * 128 + 64 + j] = f2tf(v - __uint_as_float(h));
}

// ---------------- GEMM1: h1 = x @ W1, [NN,256]@[256,64], 2xTF32, cp.async ----------
// BM=128, BK=16, BN=64. 8 warps: wm 0..3 (32 rows), wn 0..1 (32 cols).
// A: single TF32 (ah only); B: hi+lo pre-split. Terms: ah*bh + ah*bl.
// Dropped al*bh costs ~2.8e-4 RMS relative on h1 (random-sign over K=256) — well
// under the 1e-3 gate combined with fp16 storage. -33% tensor work, -40% in-loop ALU.
__global__ __launch_bounds__(256, 3) void gemm1_tc(const float* __restrict__ X,
                                                   const float* __restrict__ A1S,
                                                   const float* __restrict__ A1D) {
    __shared__ float    As[2][128][20];   // stride 20: conflict-free frag LDS
    __shared__ unsigned Bs[2][16][136];   // stride 136: k*8+n covers all 32 banks
    __shared__ float    s_sm[2][128];
    __shared__ float    d_sm[2][128];

    const int t    = threadIdx.x;
    const int lane = t & 31;
    const int w    = t >> 5;
    const int wm   = w >> 1;
    const int wn   = w & 1;
    const int m0   = blockIdx.x * 128;

    // per-thread load coordinates
    const int ar0 = t >> 2,          ac0 = (t & 3) << 2;          // A chunk 0
    const int ar1 = (t + 256) >> 2,  ac1 = ((t + 256) & 3) << 2;  // A chunk 1
    const int br0 = t >> 5,          bq0 = (t & 31) << 2;         // B chunk 0 (rows 0-7)
    const int br1 = br0 + 8;                                      // B chunk 1 (rows 8-15)
    const int gr0 = m0 + ar0, gr1 = m0 + ar1;
    const bool ok0 = gr0 < NN, ok1 = gr1 < NN;

    auto load_tile = [&](int kc, int st) {
        cpa16(&As[st][ar0][ac0], X + (size_t)(ok0 ? gr0 : 0) * FIN + kc + ac0, ok0);
        cpa16(&As[st][ar1][ac1], X + (size_t)(ok1 ? gr1 : 0) * FIN + kc + ac1, ok1);
        cpa16(&Bs[st][br0][bq0], &g_W1hl[(kc + br0) * 128 + bq0], true);
        cpa16(&Bs[st][br1][bq0], &g_W1hl[(kc + br1) * 128 + bq0], true);
    };

    float acc[2][4][4];
    #pragma unroll
    for (int i = 0; i < 2; i++)
        #pragma unroll
        for (int j = 0; j < 4; j++)
            #pragma unroll
            for (int k = 0; k < 4; k++) acc[i][j][k] = 0.0f;

    load_tile(0, 0);
    cpa_commit();

    int cur = 0;
    for (int tile = 0; tile < 16; tile++) {
        if (tile < 15) {
            load_tile((tile + 1) * 16, cur ^ 1);
            cpa_commit();
            cpa_wait<1>();
        } else {
            cpa_wait<0>();
        }
        __syncthreads();

        #pragma unroll
        for (int ks = 0; ks < 2; ks++) {
            unsigned bh[4][2], bl[4][2];
            #pragma unroll
            for (int nt = 0; nt < 4; nt++) {
                int n = wn * 32 + nt * 8 + (lane >> 2);
                int k = ks * 8 + (lane & 3);
                bh[nt][0] = Bs[cur][k][n];          bh[nt][1] = Bs[cur][k + 4][n];
                bl[nt][0] = Bs[cur][k][64 + n];     bl[nt][1] = Bs[cur][k + 4][64 + n];
            }
            #pragma unroll
            for (int mt = 0; mt < 2; mt++) {
                int r = wm * 32 + mt * 16 + (lane >> 2);
                int c = ks * 8 + (lane & 3);
                unsigned ah[4];
                ah[0] = f2tf(As[cur][r][c]);
                ah[1] = f2tf(As[cur][r + 8][c]);
                ah[2] = f2tf(As[cur][r][c + 4]);
                ah[3] = f2tf(As[cur][r + 8][c + 4]);
                #pragma unroll
                for (int nt = 0; nt < 4; nt++) {
                    mma_tf32(acc[mt][nt], ah, bh[nt]);
                    mma_tf32(acc[mt][nt], ah, bl[nt]);
                }
            }
        }
        __syncthreads();
        cur ^= 1;
    }

    // epilogue: store h1 (half2) + fused s/d dot products (from fp32 accs)
    float a_s[8], a_d[8];
    #pragma unroll
    for (int nt = 0; nt < 4; nt++) {
        int c0 = wn * 32 + nt * 8 + (lane & 3) * 2;
        a_s[nt * 2]     = A1S[c0];
        a_s[nt * 2 + 1] = A1S[c0 + 1];
        a_d[nt * 2]     = A1D[c0];
        a_d[nt * 2 + 1] = A1D[c0 + 1];
    }

    #pragma unroll
    for (int mt = 0; mt < 2; mt++) {
        int r0 = m0 + wm * 32 + mt * 16 + (lane >> 2);
        float sp0 = 0.f, dp0 = 0.f, sp1 = 0.f, dp1 = 0.f;
        #pragma unroll
        for (int nt = 0; nt < 4; nt++) {
            int cp = wn * 16 + nt * 4 + (lane & 3);   // half2 column index
            if (r0 < NN)
                g_h1h[(size_t)r0 * 32 + cp] = pkh2(acc[mt][nt][0], acc[mt][nt][1]);
            if (r0 + 8 < NN)
                g_h1h[(size_t)(r0 + 8) * 32 + cp] = pkh2(acc[mt][nt][2], acc[mt][nt][3]);
            sp0 = fmaf(acc[mt][nt][0], a_s[nt * 2],     sp0);
            sp0 = fmaf(acc[mt][nt][1], a_s[nt * 2 + 1], sp0);
            sp1 = fmaf(acc[mt][nt][2], a_s[nt * 2],     sp1);
            sp1 = fmaf(acc[mt][nt][3], a_s[nt * 2 + 1], sp1);
            dp0 = fmaf(acc[mt][nt][0], a_d[nt * 2],     dp0);
            dp0 = fmaf(acc[mt][nt][1], a_d[nt * 2 + 1], dp0);
            dp1 = fmaf(acc[mt][nt][2], a_d[nt * 2],     dp1);
            dp1 = fmaf(acc[mt][nt][3], a_d[nt * 2 + 1], dp1);
        }
        #pragma unroll
        for (int off = 1; off < 4; off <<= 1) {
            sp0 += __shfl_xor_sync(0xffffffffu, sp0, off);
            sp1 += __shfl_xor_sync(0xffffffffu, sp1, off);
            dp0 += __shfl_xor_sync(0xffffffffu, dp0, off);
            dp1 += __shfl_xor_sync(0xffffffffu, dp1, off);
        }
        if ((lane & 3) == 0) {
            int lr = wm * 32 + mt * 16 + (lane >> 2);
            s_sm[wn][lr]     = sp0;
            s_sm[wn][lr + 8] = sp1;
            d_sm[wn][lr]     = dp0;
            d_sm[wn][lr + 8] = dp1;
        }
    }
    __syncthreads();
    if (t < 128) {
        int gr = m0 + t;
        if (gr < NN) {
            g_s1[gr] = s_sm[0][t] + s_sm[1][t];
            g_d1[gr] = d_sm[0][t] + d_sm[1][t];
        }
    }
}

// ---------------- GEMM2: h2 = out1 @ W2 (out1 already relu'd), fused s2/d2 ----------
// h2 stored as packed half2; s2/d2 from fp32 accumulators.
__global__ __launch_bounds__(320) void gemm2_kernel(const float* __restrict__ W2,
                                                    const float* __restrict__ A2S,
                                                    const float* __restrict__ A2D) {
    __shared__ float hs[64][65];
    __shared__ unsigned long long ws2[64][20];
    __shared__ float s_sm2[10][64];
    __shared__ float d_sm2[10][64];
    const int t  = threadIdx.x;              // 320 threads
    const int tx = t % 10;
    const int ty = t / 10;
    const int m0 = blockIdx.x * 64;

    for (int idx = t; idx < 64 * 64; idx += 320) {
        int r = idx >> 6, c = idx & 63;
        int gr = m0 + r;
        hs[r][c] = (gr < NN) ? g_out1[(size_t)gr * HID + c] : 0.0f;
    }
    for (int idx = t; idx < 64 * 20; idx += 320) {
        int r = idx / 20, j = idx % 20;
        float2 v = *(const float2*)(W2 + (size_t)r * NC + j * 2);
        ws2[r][j] = pk2(v.x, v.y);
    }
    __syncthreads();

    if (ty < 32) {
        unsigned long long acc[2][2] = {{0ull, 0ull}, {0ull, 0ull}};
        #pragma unroll
        for (int k = 0; k < 64; k++) {
            unsigned long long b0 = ws2[k][tx * 2];
            unsigned long long b1 = ws2[k][tx * 2 + 1];
            #pragma unroll
            for (int i = 0; i < 2; i++) {
                float a = hs[ty * 2 + i][k];
                unsigned long long aa = pk2(a, a);
                acc[i][0] = ffma2(aa, b0, acc[i][0]);
                acc[i][1] = ffma2(aa, b1, acc[i][1]);
            }
        }
        float as0 = A2S[tx * 4], as1 = A2S[tx * 4 + 1], as2 = A2S[tx * 4 + 2], as3 = A2S[tx * 4 + 3];
        float ad0 = A2D[tx * 4], ad1 = A2D[tx * 4 + 1], ad2 = A2D[tx * 4 + 2], ad3 = A2D[tx * 4 + 3];
        #pragma unroll
        for (int i = 0; i < 2; i++) {
            int row = m0 + ty * 2 + i;
            float2 lo = upk2(acc[i][0]);
            float2 hi = upk2(acc[i][1]);
            if (row < NN) {
                uint2 hv = make_uint2(pkh2(lo.x, lo.y), pkh2(hi.x, hi.y));
                *(uint2*)(g_h2h + (size_t)row * 20 + tx * 2) = hv;
            }
            s_sm2[tx][ty * 2 + i] = lo.x * as0 + lo.y * as1 + hi.x * as2 + hi.y * as3;
            d_sm2[tx][ty * 2 + i] = lo.x * ad0 + lo.y * ad1 + hi.x * ad2 + hi.y * ad3;
        }
    }
    __syncthreads();
    if (t < 64) {
        int gr = m0 + t;
        if (gr < NN) {
            float ss = 0.f, dd = 0.f;
            #pragma unroll
            for (int j = 0; j < 10; j++) { ss += s_sm2[j][t]; dd += d_sm2[j][t]; }
            g_s2[gr] = ss;
            g_d2[gr] = dd;
        }
    }
}

// ---------------- aggregation: warp per dst node, fused pass, MLP=8, half2 H --------
// H rows are packed half2 (D/2 words). Lane covers 2 feature cols = one 4B load/edge.
// x8-unrolled broadcast loop: 8 independent gathers in flight per warp. Dummy lanes
// carry (w=0, src=0) -> harmless L1-resident H[0] loads.
template <int D, bool RELU>
__global__ __launch_bounds__(256) void agg_kernel(const unsigned* __restrict__ H,
                                                  const float* __restrict__ S,
                                                  const float* __restrict__ DA,
                                                  float* __restrict__ OUT) {
    constexpr int DH = D / 2;
    int v    = (blockIdx.x * blockDim.x + threadIdx.x) >> 5;
    int lane = threadIdx.x & 31;
    if (v >= NN) return;
    int p0 = g_rowptr[v], p1 = g_rowptr[v + 1];
    float dv = DA[v];

    int cp = lane < DH ? lane : DH - 1;   // clamp (D=40: lanes 20..31 duplicate)

    float2 acc = make_float2(0.0f, 0.0f);
    float denom = 0.0f;

    for (int base = p0; base < p1; base += 32) {
        int p = base + lane;
        float wl = 0.0f;
        int   svl = 0;
        if (p < p1) {
            int2 e = g_edge[p];
            svl = e.x;
            float sc = S[svl] + dv;
            sc = sc > 0.0f ? sc : 0.2f * sc;
            float el = __expf(sc);
            denom += el;                               // denominator: exp only (no ew)
            wl = el * __int_as_float(e.y);             // numerator weight: exp * ew
        }
        int nj  = p1 - base; if (nj > 32) nj = 32;
        int njp = (nj + 7) & ~7;             // pad to x8: extra lanes have w=0, src=0
        for (int j = 0; j < njp; j += 8) {
            float wb[8]; int sb[8];
            #pragma unroll
            for (int q = 0; q < 8; q++) {
                wb[q] = __shfl_sync(0xffffffffu, wl, j + q);
                sb[q] = __shfl_sync(0xffffffffu, svl, j + q);
            }
            float2 hb[8];
            #pragma unroll
            for (int q = 0; q < 8; q++)
                hb[q] = uph2(H[(size_t)sb[q] * DH + cp]);
            #pragma unroll
            for (int q = 0; q < 8; q++) {
                acc.x = fmaf(wb[q], hb[q].x, acc.x);
                acc.y = fmaf(wb[q], hb[q].y, acc.y);
            }
        }
    }
    #pragma unroll
    for (int off = 16; off; off >>= 1)
        denom += __shfl_xor_sync(0xffffffffu, denom, off);
    float inv = 1.0f / denom;   // >0 guaranteed: every node has a self loop

    if (lane < DH) {
        float ox = acc.x * inv, oy = acc.y * inv;
        if (RELU) { ox = ox > 0.f ? ox : 0.f; oy = oy > 0.f ? oy : 0.f; }
        *(float2*)(OUT + (size_t)v * D + lane * 2) = make_float2(ox, oy);
    }
}

// ---------------- launch ----------------
extern "C" void kernel_launch(void* const* d_in, const int* in_sizes, int n_in,
                              void* d_out, int out_size) {
    const float* x   = (const float*)d_in[0];
    const int*   ei  = (const int*)  d_in[1];
    const float* ew  = (const float*)d_in[2];
    const float* W1  = (const float*)d_in[3];
    const float* a1s = (const float*)d_in[4];
    const float* a1d = (const float*)d_in[5];
    const float* W2  = (const float*)d_in[6];
    const float* a2s = (const float*)d_in[7];
    const float* a2d = (const float*)d_in[8];
    float* out = (float*)d_out;

    const int* srcA = ei;
    const int* dstA = ei + EE;

    unsigned *ph1h, *ph2h;
    float *pout1, *ps1, *pd1, *ps2, *pd2;
    cudaGetSymbolAddress((void**)&ph1h,  g_h1h);
    cudaGetSymbolAddress((void**)&pout1, g_out1);
    cudaGetSymbolAddress((void**)&ph2h,  g_h2h);
    cudaGetSymbolAddress((void**)&ps1,   g_s1);
    cudaGetSymbolAddress((void**)&pd1,   g_d1);
    cudaGetSymbolAddress((void**)&ps2,   g_s2);
    cudaGetSymbolAddress((void**)&pd2,   g_d2);

    // Capture-safe side stream + fork/join events
    static cudaStream_t s2 = nullptr;
    static cudaEvent_t  evF = nullptr, evJ = nullptr;
    if (!s2) {
        cudaStreamCreateWithFlags(&s2, cudaStreamNonBlocking);
        cudaEventCreateWithFlags(&evF, cudaEventDisableTiming);
        cudaEventCreateWithFlags(&evJ, cudaEventDisableTiming);
    }

    const int TPB = 256;
    const int nb  = (NN + 1023) / 1024;

    // Fork: CSR build on side stream; W1 pre-split + gemm1 on main stream
    cudaEventRecord(evF, 0);
    cudaStreamWaitEvent(s2, evF, 0);
    zero_cnt_kernel<<<(NN + TPB - 1) / TPB, TPB, 0, s2>>>();
    hist_kernel<<<(ET + TPB - 1) / TPB, TPB, 0, s2>>>(dstA);
    scan1_kernel<<<nb, 1024, 0, s2>>>();
    convw1_kernel<<<(FIN * HID + TPB - 1) / TPB, TPB>>>(W1);    // main stream, tiny
    gemm1_tc<<<(NN + 127) / 128, 256>>>(x, a1s, a1d);           // main stream
    scan23_kernel<<<nb, 1024, 0, s2>>>(nb);
    fill_kernel<<<(ET + TPB - 1) / TPB, TPB, 0, s2>>>(srcA, dstA, ew);
    cudaEventRecord(evJ, s2);

    // Join, then the serial tail
    cudaStreamWaitEvent(0, evJ, 0);
    agg_kernel<HID, true><<<(NN * 32 + TPB - 1) / TPB, TPB>>>(ph1h, ps1, pd1, pout1);
    gemm2_kernel<<<(NN + 63) / 64, 320>>>(W2, a2s, a2d);
    agg_kernel<NC, false><<<(NN * 32 + TPB - 1) / TPB, TPB>>>(ph2h, ps2, pd2, out);
}